// round 12
// baseline (speedup 1.0000x reference)
#include <cuda_runtime.h>
#include <cuda_bf16.h>
#include <mma.h>
#include <stdint.h>
#include <math.h>
using namespace nvcuda;

#define NTH 256

__device__ __nv_bfloat16 g_ewh[256 * 512], g_ewl[256 * 512];
__device__ __nv_bfloat16 g_dwh[512 * 256], g_dwl[512 * 256];
__device__ __nv_bfloat16 g_mh[64 * 256],  g_ml[64 * 256];

#define XH(b)  ((b) * 10240)
#define XL(b)  ((b) * 10240 + 5120)
#define WH(b)  (20480 + (b) * 40960)
#define WL(b)  (40960 + (b) * 40960)
#define STG_O  0
#define MEMH_O 20480
#define MEML_O 54272
#define EBH_O  88064
#define EBL_O  97280
#define ATH_O  88064
#define ATL_O  97280
#define MH_O   20480
#define ML_O   54272
#define B4H(b) ((b) ? 88064 : 0)
#define B4L(b) ((b) ? 98304 : 10240)
#define SMEM_TOTAL 108544

typedef wmma::fragment<wmma::matrix_a, 16,16,16, __nv_bfloat16, wmma::row_major> FragA;
typedef wmma::fragment<wmma::matrix_b, 16,16,16, __nv_bfloat16, wmma::col_major> FragBc;
typedef wmma::fragment<wmma::matrix_b, 16,16,16, __nv_bfloat16, wmma::row_major> FragBr;
typedef wmma::fragment<wmma::accumulator, 16,16,16, float> FragC;

__device__ __forceinline__ float tanh_fast(float x) {
    float r;
    asm("tanh.approx.f32 %0, %1;" : "=f"(r) : "f"(x));
    return r;
}
__device__ __forceinline__ uint32_t bfpair(float a, float b) {
    __nv_bfloat162 t = __floats2bfloat162_rn(a, b);
    return *reinterpret_cast<uint32_t*>(&t);
}
__device__ __forceinline__ void split4(const float4 v, uint2 &h, uint2 &l) {
    __nv_bfloat16 hx = __float2bfloat16(v.x), hy = __float2bfloat16(v.y);
    __nv_bfloat16 hz = __float2bfloat16(v.z), hw = __float2bfloat16(v.w);
    h.x = ((uint32_t)__bfloat16_as_ushort(hy) << 16) | (uint32_t)__bfloat16_as_ushort(hx);
    h.y = ((uint32_t)__bfloat16_as_ushort(hw) << 16) | (uint32_t)__bfloat16_as_ushort(hz);
    l.x = bfpair(v.x - __bfloat162float(hx), v.y - __bfloat162float(hy));
    l.y = bfpair(v.z - __bfloat162float(hz), v.w - __bfloat162float(hw));
}
__device__ __forceinline__ void split1(float v, uint16_t &h, uint16_t &l) {
    __nv_bfloat16 hv = __float2bfloat16(v);
    h = __bfloat16_as_ushort(hv);
    l = __bfloat16_as_ushort(__float2bfloat16(v - __bfloat162float(hv)));
}
// split a pair (a,b) -> packed bf16x2 hi and lo words
__device__ __forceinline__ void split2(float a, float b, uint32_t &hw, uint32_t &lw) {
    __nv_bfloat16 ha = __float2bfloat16(a), hb = __float2bfloat16(b);
    hw = ((uint32_t)__bfloat16_as_ushort(hb) << 16) | (uint32_t)__bfloat16_as_ushort(ha);
    lw = bfpair(a - __bfloat162float(ha), b - __bfloat162float(hb));
}
__device__ __forceinline__ void cpa(uint32_t s, const void* g) {
    asm volatile("cp.async.ca.shared.global [%0], [%1], 16;" :: "r"(s), "l"(g));
}
__device__ __forceinline__ void cpcommit() { asm volatile("cp.async.commit_group;"); }
template<int N> __device__ __forceinline__ void cpwait() {
    asm volatile("cp.async.wait_group %0;" :: "n"(N));
}

__global__ void split_small(const float4* __restrict__ ew, const float4* __restrict__ dw,
                            const float4* __restrict__ mw) {
    int i = blockIdx.x * blockDim.x + threadIdx.x;
    if (i < 32768) {
        uint2 h, l; split4(ew[i], h, l);
        ((uint2*)g_ewh)[i] = h; ((uint2*)g_ewl)[i] = l;
    } else if (i < 65536) {
        int j = i - 32768;
        uint2 h, l; split4(dw[j], h, l);
        ((uint2*)g_dwh)[j] = h; ((uint2*)g_dwl)[j] = l;
    } else if (i < 69632) {
        int j = i - 65536;
        uint2 h, l; split4(mw[j], h, l);
        ((uint2*)g_mh)[j] = h; ((uint2*)g_ml)[j] = l;
    }
}

__global__ __launch_bounds__(NTH, 2)
void mwm8(const float* __restrict__ seq,
          const float* __restrict__ enc_b_, const float* __restrict__ dec_b_,
          float* __restrict__ recon, float* __restrict__ att, float* __restrict__ memout)
{
    extern __shared__ char smem[];
    uint32_t sb;
    asm("{ .reg .u64 t; cvta.to.shared.u64 t, %1; cvt.u32.u64 %0, t; }" : "=r"(sb) : "l"(smem));
    const int tid = threadIdx.x, wid = tid >> 5;
    const int wm = wid & 1, wn = wid >> 1;
    const int rm = wm * 32;
    const int lane = tid & 31;
    const int r0f = lane >> 2, c0f = (lane & 3) * 2;   // m16n16 f32 acc layout
    const long row0 = (long)blockIdx.x * 64;

    const int xr = tid >> 2, xq = (tid & 3) * 8;
    const float* xsrc = seq + (row0 + xr) * 512 + xq;

    auto xconv = [&](float4* rx, int b) {
        uint2 h0, l0, h1, l1;
        split4(rx[0], h0, l0);
        split4(rx[1], h1, l1);
        __nv_bfloat16* Xh = (__nv_bfloat16*)(smem + XH(b));
        __nv_bfloat16* Xl = (__nv_bfloat16*)(smem + XL(b));
        *(uint2*)(Xh + xr * 40 + xq)     = h0;
        *(uint2*)(Xh + xr * 40 + xq + 4) = h1;
        *(uint2*)(Xl + xr * 40 + xq)     = l0;
        *(uint2*)(Xl + xr * 40 + xq + 4) = l1;
    };

    // ================== GEMM1 mainloop (R11 verbatim) ==================
    FragC acc1[2][4];
    #pragma unroll
    for (int t = 0; t < 2; t++)
        #pragma unroll
        for (int f = 0; f < 4; f++) wmma::fill_fragment(acc1[t][f], 0.0f);

    float4 rx[2][2];
    {
        rx[0][0] = *(const float4*)(xsrc);
        rx[0][1] = *(const float4*)(xsrc + 4);
        rx[1][0] = *(const float4*)(xsrc + 32);
        rx[1][1] = *(const float4*)(xsrc + 36);
        xconv(rx[0], 0);
        #pragma unroll
        for (int i = 0; i < 4; i++) {
            int o = tid + i * NTH, wr = o >> 2, ws = o & 3;
            cpa(sb + WH(0) + wr * 80 + ws * 16, g_ewh + wr * 512 + ws * 8);
            cpa(sb + WL(0) + wr * 80 + ws * 16, g_ewl + wr * 512 + ws * 8);
        }
        cpcommit();
    }
    for (int kc = 0; kc < 16; kc++) {
        const int buf = kc & 1;
        if (kc < 15) {
            const int nb = buf ^ 1, kn = kc + 1;
            #pragma unroll
            for (int i = 0; i < 4; i++) {
                int o = tid + i * NTH, wr = o >> 2, ws = o & 3;
                cpa(sb + WH(nb) + wr * 80 + ws * 16, g_ewh + wr * 512 + kn * 32 + ws * 8);
                cpa(sb + WL(nb) + wr * 80 + ws * 16, g_ewl + wr * 512 + kn * 32 + ws * 8);
            }
            cpcommit();
            xconv(rx[nb], nb);
            if (kc < 14) {
                rx[buf][0] = *(const float4*)(xsrc + (kc + 2) * 32);
                rx[buf][1] = *(const float4*)(xsrc + (kc + 2) * 32 + 4);
            }
            cpwait<1>();
        } else cpwait<0>();
        __syncthreads();
        const __nv_bfloat16* Xh = (const __nv_bfloat16*)(smem + XH(buf));
        const __nv_bfloat16* Xl = (const __nv_bfloat16*)(smem + XL(buf));
        const __nv_bfloat16* Wh = (const __nv_bfloat16*)(smem + WH(buf));
        const __nv_bfloat16* Wl = (const __nv_bfloat16*)(smem + WL(buf));
        #pragma unroll
        for (int ks = 0; ks < 2; ks++) {
            FragA ah[2], al[2];
            #pragma unroll
            for (int t = 0; t < 2; t++) {
                wmma::load_matrix_sync(ah[t], Xh + (rm + 16 * t) * 40 + ks * 16, 40);
                wmma::load_matrix_sync(al[t], Xl + (rm + 16 * t) * 40 + ks * 16, 40);
            }
            #pragma unroll
            for (int f = 0; f < 4; f++) {
                FragBc bh, bl;
                wmma::load_matrix_sync(bh, Wh + (wn * 64 + f * 16) * 40 + ks * 16, 40);
                wmma::load_matrix_sync(bl, Wl + (wn * 64 + f * 16) * 40 + ks * 16, 40);
                #pragma unroll
                for (int t = 0; t < 2; t++) {
                    wmma::mma_sync(acc1[t][f], ah[t], bh, acc1[t][f]);
                    wmma::mma_sync(acc1[t][f], ah[t], bl, acc1[t][f]);
                    wmma::mma_sync(acc1[t][f], al[t], bh, acc1[t][f]);
                }
            }
        }
        __syncthreads();
    }

    // ---- load memory bank tile [64][264] h/l ----
    #pragma unroll
    for (int i = 0; i < 8; i++) {
        int o = tid + i * NTH, s = o >> 5, c8 = o & 31;
        cpa(sb + MEMH_O + s * 528 + c8 * 16, g_mh + s * 256 + c8 * 8);
        cpa(sb + MEML_O + s * 528 + c8 * 16, g_ml + s * 256 + c8 * 8);
    }
    cpcommit();

    // ====== GEMM1 epilogue fused with GEMM2: DIRECT fragment conversion ======
    FragC acc2[2];
    wmma::fill_fragment(acc2[0], 0.0f);
    wmma::fill_fragment(acc2[1], 0.0f);
    {
        __nv_bfloat16* Ebh = (__nv_bfloat16*)(smem + EBH_O);
        __nv_bfloat16* Ebl = (__nv_bfloat16*)(smem + EBL_O);
        const __nv_bfloat16* Mh = (const __nv_bfloat16*)(smem + MEMH_O);
        const __nv_bfloat16* Ml = (const __nv_bfloat16*)(smem + MEML_O);
        for (int b = 0; b < 4; b++) {
            if (wn == b) {
                #pragma unroll
                for (int t = 0; t < 2; t++)
                    #pragma unroll
                    for (int f = 0; f < 4; f++) {
                        const float* xf = acc1[t][f].x;
                        #pragma unroll
                        for (int p = 0; p < 4; p++) {
                            int r = rm + 16 * t + r0f + (p & 1) * 8;
                            int c = f * 16 + c0f + (p >> 1) * 8;    // col within block
                            int gc = b * 64 + c;
                            float e0 = tanh_fast(xf[2 * p]     + __ldg(enc_b_ + gc));
                            float e1 = tanh_fast(xf[2 * p + 1] + __ldg(enc_b_ + gc + 1));
                            uint32_t hw, lw; split2(e0, e1, hw, lw);
                            *(uint32_t*)(Ebh + r * 72 + c) = hw;
                            *(uint32_t*)(Ebl + r * 72 + c) = lw;
                        }
                    }
            }
            if (b == 0) cpwait<0>();
            __syncthreads();
            #pragma unroll
            for (int ks = 0; ks < 4; ks++) {
                FragA ah[2], al[2];
                #pragma unroll
                for (int t = 0; t < 2; t++) {
                    wmma::load_matrix_sync(ah[t], Ebh + (rm + 16 * t) * 72 + ks * 16, 72);
                    wmma::load_matrix_sync(al[t], Ebl + (rm + 16 * t) * 72 + ks * 16, 72);
                }
                FragBc bh, bl;
                wmma::load_matrix_sync(bh, Mh + (wn * 16) * 264 + b * 64 + ks * 16, 264);
                wmma::load_matrix_sync(bl, Ml + (wn * 16) * 264 + b * 64 + ks * 16, 264);
                #pragma unroll
                for (int t = 0; t < 2; t++) {
                    wmma::mma_sync(acc2[t], ah[t], bh, acc2[t]);
                    wmma::mma_sync(acc2[t], ah[t], bl, acc2[t]);
                    wmma::mma_sync(acc2[t], al[t], bh, acc2[t]);
                }
            }
            __syncthreads();
        }
        // logits -> stg (cross-warp rows need smem)
        float* stg = (float*)(smem + STG_O);
        #pragma unroll
        for (int t = 0; t < 2; t++)
            wmma::store_matrix_sync(stg + (rm + 16 * t) * 68 + wn * 16, acc2[t], 68,
                                    wmma::mem_row_major);
        __syncthreads();
    }

    // ====== softmax (threads 0..63) + attn tiles (R11 verbatim) ======
    {
        __nv_bfloat16* Ah = (__nv_bfloat16*)(smem + ATH_O);
        __nv_bfloat16* Al = (__nv_bfloat16*)(smem + ATL_O);
        if (tid < 64) {
            float* lr = (float*)(smem + STG_O) + tid * 68;
            float m = -1e30f;
            #pragma unroll
            for (int c = 0; c < 64; c++) m = fmaxf(m, lr[c]);
            float sum = 0.f;
            #pragma unroll
            for (int c = 0; c < 64; c++) {
                float e = __expf((lr[c] - m) * 0.0625f);
                lr[c] = e; sum += e;
            }
            float inv = 1.0f / sum;
            float* arow = att + (row0 + tid) * 64;
            #pragma unroll
            for (int c = 0; c < 64; c += 4) {
                float4 v = *(float4*)(lr + c);
                v.x *= inv; v.y *= inv; v.z *= inv; v.w *= inv;
                *(float4*)(arow + c) = v;
                uint16_t h, l;
                split1(v.x, h, l); Ah[tid*72+c]   = __ushort_as_bfloat16(h); Al[tid*72+c]   = __ushort_as_bfloat16(l);
                split1(v.y, h, l); Ah[tid*72+c+1] = __ushort_as_bfloat16(h); Al[tid*72+c+1] = __ushort_as_bfloat16(l);
                split1(v.z, h, l); Ah[tid*72+c+2] = __ushort_as_bfloat16(h); Al[tid*72+c+2] = __ushort_as_bfloat16(l);
                split1(v.w, h, l); Ah[tid*72+c+3] = __ushort_as_bfloat16(h); Al[tid*72+c+3] = __ushort_as_bfloat16(l);
            }
        }
        __syncthreads();
    }

    // ---- prefetch GEMM4 q=0 into buf0 ----
    #pragma unroll
    for (int i = 0; i < 2; i++) {
        int o = tid + i * NTH, r = o >> 2, sg = o & 3;
        cpa(sb + B4H(0) + r * 80 + sg * 16, g_dwh + r * 256 + sg * 8);
        cpa(sb + B4L(0) + r * 80 + sg * 16, g_dwl + r * 256 + sg * 8);
    }
    cpcommit();

    // ================== GEMM3: M = attn @ mem (R11 verbatim) ==================
    FragC acc3[2][4];
    #pragma unroll
    for (int t = 0; t < 2; t++)
        #pragma unroll
        for (int f = 0; f < 4; f++) wmma::fill_fragment(acc3[t][f], 0.0f);
    {
        const __nv_bfloat16* Ah = (const __nv_bfloat16*)(smem + ATH_O);
        const __nv_bfloat16* Al = (const __nv_bfloat16*)(smem + ATL_O);
        const __nv_bfloat16* Mh = (const __nv_bfloat16*)(smem + MEMH_O);
        const __nv_bfloat16* Ml = (const __nv_bfloat16*)(smem + MEML_O);
        #pragma unroll
        for (int ks = 0; ks < 4; ks++) {
            FragA ah[2], al[2];
            #pragma unroll
            for (int t = 0; t < 2; t++) {
                wmma::load_matrix_sync(ah[t], Ah + (rm + 16 * t) * 72 + ks * 16, 72);
                wmma::load_matrix_sync(al[t], Al + (rm + 16 * t) * 72 + ks * 16, 72);
            }
            #pragma unroll
            for (int f = 0; f < 4; f++) {
                FragBr bh, bl;
                wmma::load_matrix_sync(bh, Mh + (ks * 16) * 264 + wn * 64 + f * 16, 264);
                wmma::load_matrix_sync(bl, Ml + (ks * 16) * 264 + wn * 64 + f * 16, 264);
                #pragma unroll
                for (int t = 0; t < 2; t++) {
                    wmma::mma_sync(acc3[t][f], ah[t], bh, acc3[t][f]);
                    wmma::mma_sync(acc3[t][f], ah[t], bl, acc3[t][f]);
                    wmma::mma_sync(acc3[t][f], al[t], bh, acc3[t][f]);
                }
            }
        }
    }
    __syncthreads();   // all warps done reading mem tile -> M region writable

    // ---- M epilogue: DIRECT fragment conversion (one trailing sync) ----
    {
        __nv_bfloat16* Mh = (__nv_bfloat16*)(smem + MH_O);
        __nv_bfloat16* Ml = (__nv_bfloat16*)(smem + ML_O);
        #pragma unroll
        for (int t = 0; t < 2; t++)
            #pragma unroll
            for (int f = 0; f < 4; f++) {
                const float* xf = acc3[t][f].x;
                #pragma unroll
                for (int p = 0; p < 4; p++) {
                    int r = rm + 16 * t + r0f + (p & 1) * 8;
                    int c = wn * 64 + f * 16 + c0f + (p >> 1) * 8;
                    float v0 = xf[2 * p], v1 = xf[2 * p + 1];
                    *(float2*)(memout + (row0 + r) * 256 + c) = make_float2(v0, v1);
                    uint32_t hw, lw; split2(v0, v1, hw, lw);
                    *(uint32_t*)(Mh + r * 264 + c) = hw;
                    *(uint32_t*)(Ml + r * 264 + c) = lw;
                }
            }
    }
    __syncthreads();   // M tiles complete before G4 reads them

    // ================== GEMM4: recon = M @ dec_w^T + dec_b ==================
    {
        const __nv_bfloat16* Mh = (const __nv_bfloat16*)(smem + MH_O);
        const __nv_bfloat16* Ml = (const __nv_bfloat16*)(smem + ML_O);
        FragC acc4[2][2];
        for (int q = 0; q < 32; q++) {
            const int nt = q >> 3, kc = q & 7, buf = q & 1;
            if (kc == 0) {
                #pragma unroll
                for (int t = 0; t < 2; t++)
                    #pragma unroll
                    for (int f = 0; f < 2; f++) wmma::fill_fragment(acc4[t][f], 0.0f);
            }
            if (q < 31) {
                const int qp = q + 1, ntn = qp >> 3, kcn = qp & 7, nb = buf ^ 1;
                #pragma unroll
                for (int i = 0; i < 2; i++) {
                    int o = tid + i * NTH, r = o >> 2, sg = o & 3;
                    cpa(sb + B4H(nb) + r * 80 + sg * 16,
                        g_dwh + (ntn * 128 + r) * 256 + kcn * 32 + sg * 8);
                    cpa(sb + B4L(nb) + r * 80 + sg * 16,
                        g_dwl + (ntn * 128 + r) * 256 + kcn * 32 + sg * 8);
                }
                cpcommit(); cpwait<1>();
            } else cpwait<0>();
            __syncthreads();
            const __nv_bfloat16* Bh = (const __nv_bfloat16*)(smem + B4H(buf));
            const __nv_bfloat16* Bl = (const __nv_bfloat16*)(smem + B4L(buf));
            #pragma unroll
            for (int ks = 0; ks < 2; ks++) {
                FragA ah[2], al[2];
                #pragma unroll
                for (int t = 0; t < 2; t++) {
                    wmma::load_matrix_sync(ah[t], Mh + (rm + 16 * t) * 264 + kc * 32 + ks * 16, 264);
                    wmma::load_matrix_sync(al[t], Ml + (rm + 16 * t) * 264 + kc * 32 + ks * 16, 264);
                }
                #pragma unroll
                for (int f = 0; f < 2; f++) {
                    FragBc bh, bl;
                    wmma::load_matrix_sync(bh, Bh + (wn * 32 + f * 16) * 40 + ks * 16, 40);
                    wmma::load_matrix_sync(bl, Bl + (wn * 32 + f * 16) * 40 + ks * 16, 40);
                    #pragma unroll
                    for (int t = 0; t < 2; t++) {
                        wmma::mma_sync(acc4[t][f], ah[t], bh, acc4[t][f]);
                        wmma::mma_sync(acc4[t][f], ah[t], bl, acc4[t][f]);
                        wmma::mma_sync(acc4[t][f], al[t], bh, acc4[t][f]);
                    }
                }
            }
            __syncthreads();
            if (kc == 7) {
                // DIRECT register epilogue — no smem, no extra syncs
                #pragma unroll
                for (int t = 0; t < 2; t++)
                    #pragma unroll
                    for (int f = 0; f < 2; f++) {
                        const float* xf = acc4[t][f].x;
                        #pragma unroll
                        for (int p = 0; p < 4; p++) {
                            int r = rm + 16 * t + r0f + (p & 1) * 8;
                            int d = nt * 128 + wn * 32 + f * 16 + c0f + (p >> 1) * 8;
                            float v0 = xf[2 * p]     + __ldg(dec_b_ + d);
                            float v1 = xf[2 * p + 1] + __ldg(dec_b_ + d + 1);
                            *(float2*)(recon + (row0 + r) * 512 + d) = make_float2(v0, v1);
                        }
                    }
            }
        }
    }
}

extern "C" void kernel_launch(void* const* d_in, const int* in_sizes, int n_in,
                              void* d_out, int out_size)
{
    const float* seq   = (const float*)d_in[0];
    const float* enc_w = (const float*)d_in[1];
    const float* enc_b = (const float*)d_in[2];
    const float* memw  = (const float*)d_in[3];
    const float* dec_w = (const float*)d_in[4];
    const float* dec_b = (const float*)d_in[5];

    const long R = (long)in_sizes[0] / 512;   // 65536

    float* out    = (float*)d_out;
    float* recon  = out;
    float* att    = out + R * 512;
    float* memout = att + R * 64;

    split_small<<<272, 256>>>((const float4*)enc_w, (const float4*)dec_w, (const float4*)memw);

    cudaFuncSetAttribute(mwm8, cudaFuncAttributeMaxDynamicSharedMemorySize, SMEM_TOTAL);
    mwm8<<<(unsigned)(R / 64), NTH, SMEM_TOTAL>>>(seq, enc_b, dec_b, recon, att, memout);
}

// round 13
// speedup vs baseline: 1.0845x; 1.0845x over previous
#include <cuda_runtime.h>
#include <cuda_bf16.h>
#include <mma.h>
#include <stdint.h>
#include <math.h>
using namespace nvcuda;

#define NTH 256

__device__ __nv_bfloat16 g_ewh[256 * 512], g_ewl[256 * 512];
__device__ __nv_bfloat16 g_dwh[512 * 256], g_dwl[512 * 256];
__device__ __nv_bfloat16 g_mh[64 * 256],  g_ml[64 * 256];

#define XH(b)  ((b) * 10240)
#define WH(b)  (20480 + (b) * 40960)
#define WL(b)  (40960 + (b) * 40960)
#define STG_O  0
#define MEMH_O 20480
#define MEML_O 54272
#define EBH_O  88064
#define ATH_O  88064
#define ATL_O  97280
#define MSTG_O 88064
#define MH_O   20480
#define ML_O   54272
#define B4H(b) ((b) ? 88064 : 0)
#define B4L(b) ((b) ? 98304 : 10240)
#define SMEM_TOTAL 108544

typedef wmma::fragment<wmma::matrix_a, 16,16,16, __nv_bfloat16, wmma::row_major> FragA;
typedef wmma::fragment<wmma::matrix_b, 16,16,16, __nv_bfloat16, wmma::col_major> FragBc;
typedef wmma::fragment<wmma::matrix_b, 16,16,16, __nv_bfloat16, wmma::row_major> FragBr;
typedef wmma::fragment<wmma::accumulator, 16,16,16, float> FragC;

__device__ __forceinline__ float tanh_fast(float x) {
    float r;
    asm("tanh.approx.f32 %0, %1;" : "=f"(r) : "f"(x));
    return r;
}
__device__ __forceinline__ uint32_t bfpair(float a, float b) {
    __nv_bfloat162 t = __floats2bfloat162_rn(a, b);
    return *reinterpret_cast<uint32_t*>(&t);
}
__device__ __forceinline__ void split4(const float4 v, uint2 &h, uint2 &l) {
    __nv_bfloat16 hx = __float2bfloat16(v.x), hy = __float2bfloat16(v.y);
    __nv_bfloat16 hz = __float2bfloat16(v.z), hw = __float2bfloat16(v.w);
    h.x = ((uint32_t)__bfloat16_as_ushort(hy) << 16) | (uint32_t)__bfloat16_as_ushort(hx);
    h.y = ((uint32_t)__bfloat16_as_ushort(hw) << 16) | (uint32_t)__bfloat16_as_ushort(hz);
    l.x = bfpair(v.x - __bfloat162float(hx), v.y - __bfloat162float(hy));
    l.y = bfpair(v.z - __bfloat162float(hz), v.w - __bfloat162float(hw));
}
// hi-only pack of 4 floats -> 2 bf16x2 words
__device__ __forceinline__ uint2 pack4h(const float4 v) {
    uint2 h;
    h.x = bfpair(v.x, v.y);
    h.y = bfpair(v.z, v.w);
    return h;
}
__device__ __forceinline__ void split1(float v, uint16_t &h, uint16_t &l) {
    __nv_bfloat16 hv = __float2bfloat16(v);
    h = __bfloat16_as_ushort(hv);
    l = __bfloat16_as_ushort(__float2bfloat16(v - __bfloat162float(hv)));
}
__device__ __forceinline__ void cpa(uint32_t s, const void* g) {
    asm volatile("cp.async.ca.shared.global [%0], [%1], 16;" :: "r"(s), "l"(g));
}
__device__ __forceinline__ void cpcommit() { asm volatile("cp.async.commit_group;"); }
template<int N> __device__ __forceinline__ void cpwait() {
    asm volatile("cp.async.wait_group %0;" :: "n"(N));
}

__global__ void split_small(const float4* __restrict__ ew, const float4* __restrict__ dw,
                            const float4* __restrict__ mw) {
    int i = blockIdx.x * blockDim.x + threadIdx.x;
    if (i < 32768) {
        uint2 h, l; split4(ew[i], h, l);
        ((uint2*)g_ewh)[i] = h; ((uint2*)g_ewl)[i] = l;
    } else if (i < 65536) {
        int j = i - 32768;
        uint2 h, l; split4(dw[j], h, l);
        ((uint2*)g_dwh)[j] = h; ((uint2*)g_dwl)[j] = l;
    } else if (i < 69632) {
        int j = i - 65536;
        uint2 h, l; split4(mw[j], h, l);
        ((uint2*)g_mh)[j] = h; ((uint2*)g_ml)[j] = l;
    }
}

__global__ __launch_bounds__(NTH, 2)
void mwm9(const float* __restrict__ seq,
          const float* __restrict__ enc_b_, const float* __restrict__ dec_b_,
          float* __restrict__ recon, float* __restrict__ att, float* __restrict__ memout)
{
    extern __shared__ char smem[];
    uint32_t sb;
    asm("{ .reg .u64 t; cvta.to.shared.u64 t, %1; cvt.u32.u64 %0, t; }" : "=r"(sb) : "l"(smem));
    const int tid = threadIdx.x, wid = tid >> 5;
    const int wm = wid & 1, wn = wid >> 1;
    const int rm = wm * 32;
    const long row0 = (long)blockIdx.x * 64;

    const int xr = tid >> 2, xq = (tid & 3) * 8;
    const float* xsrc = seq + (row0 + xr) * 512 + xq;

    // X conversion: SINGLE bf16 (no low part) — GEMM1 is 2-term
    auto xconv = [&](float4* rx, int b) {
        uint2 h0 = pack4h(rx[0]);
        uint2 h1 = pack4h(rx[1]);
        __nv_bfloat16* Xh = (__nv_bfloat16*)(smem + XH(b));
        *(uint2*)(Xh + xr * 40 + xq)     = h0;
        *(uint2*)(Xh + xr * 40 + xq + 4) = h1;
    };

    // ================== GEMM1 mainloop: 2-term (Xh·Wh + Xh·Wl) ==================
    FragC acc1[2][4];
    #pragma unroll
    for (int t = 0; t < 2; t++)
        #pragma unroll
        for (int f = 0; f < 4; f++) wmma::fill_fragment(acc1[t][f], 0.0f);

    float4 rx[2][2];
    {
        rx[0][0] = *(const float4*)(xsrc);
        rx[0][1] = *(const float4*)(xsrc + 4);
        rx[1][0] = *(const float4*)(xsrc + 32);
        rx[1][1] = *(const float4*)(xsrc + 36);
        xconv(rx[0], 0);
        #pragma unroll
        for (int i = 0; i < 4; i++) {
            int o = tid + i * NTH, wr = o >> 2, ws = o & 3;
            cpa(sb + WH(0) + wr * 80 + ws * 16, g_ewh + wr * 512 + ws * 8);
            cpa(sb + WL(0) + wr * 80 + ws * 16, g_ewl + wr * 512 + ws * 8);
        }
        cpcommit();
    }
    for (int kc = 0; kc < 16; kc++) {
        const int buf = kc & 1;
        if (kc < 15) {
            const int nb = buf ^ 1, kn = kc + 1;
            #pragma unroll
            for (int i = 0; i < 4; i++) {
                int o = tid + i * NTH, wr = o >> 2, ws = o & 3;
                cpa(sb + WH(nb) + wr * 80 + ws * 16, g_ewh + wr * 512 + kn * 32 + ws * 8);
                cpa(sb + WL(nb) + wr * 80 + ws * 16, g_ewl + wr * 512 + kn * 32 + ws * 8);
            }
            cpcommit();
            xconv(rx[nb], nb);
            if (kc < 14) {
                rx[buf][0] = *(const float4*)(xsrc + (kc + 2) * 32);
                rx[buf][1] = *(const float4*)(xsrc + (kc + 2) * 32 + 4);
            }
            cpwait<1>();
        } else cpwait<0>();
        __syncthreads();
        const __nv_bfloat16* Xh = (const __nv_bfloat16*)(smem + XH(buf));
        const __nv_bfloat16* Wh = (const __nv_bfloat16*)(smem + WH(buf));
        const __nv_bfloat16* Wl = (const __nv_bfloat16*)(smem + WL(buf));
        #pragma unroll
        for (int ks = 0; ks < 2; ks++) {
            FragA ah[2];
            #pragma unroll
            for (int t = 0; t < 2; t++)
                wmma::load_matrix_sync(ah[t], Xh + (rm + 16 * t) * 40 + ks * 16, 40);
            #pragma unroll
            for (int f = 0; f < 4; f++) {
                FragBc bh, bl;
                wmma::load_matrix_sync(bh, Wh + (wn * 64 + f * 16) * 40 + ks * 16, 40);
                wmma::load_matrix_sync(bl, Wl + (wn * 64 + f * 16) * 40 + ks * 16, 40);
                #pragma unroll
                for (int t = 0; t < 2; t++) {
                    wmma::mma_sync(acc1[t][f], ah[t], bh, acc1[t][f]);
                    wmma::mma_sync(acc1[t][f], ah[t], bl, acc1[t][f]);
                }
            }
        }
        __syncthreads();
    }

    // ---- load memory bank tile [64][264] h/l ----
    #pragma unroll
    for (int i = 0; i < 8; i++) {
        int o = tid + i * NTH, s = o >> 5, c8 = o & 31;
        cpa(sb + MEMH_O + s * 528 + c8 * 16, g_mh + s * 256 + c8 * 8);
        cpa(sb + MEML_O + s * 528 + c8 * 16, g_ml + s * 256 + c8 * 8);
    }
    cpcommit();

    // ====== GEMM1 epilogue fused with GEMM2: E single bf16, GEMM2 2-pass ======
    FragC acc2[2];
    wmma::fill_fragment(acc2[0], 0.0f);
    wmma::fill_fragment(acc2[1], 0.0f);
    {
        float* stg = (float*)(smem + STG_O);
        __nv_bfloat16* Ebh = (__nv_bfloat16*)(smem + EBH_O);
        const __nv_bfloat16* Mh = (const __nv_bfloat16*)(smem + MEMH_O);
        const __nv_bfloat16* Ml = (const __nv_bfloat16*)(smem + MEML_O);
        for (int b = 0; b < 4; b++) {
            if (wn == b)
                #pragma unroll
                for (int t = 0; t < 2; t++)
                    #pragma unroll
                    for (int f = 0; f < 4; f++)
                        wmma::store_matrix_sync(stg + (rm + 16 * t) * 68 + f * 16,
                                                acc1[t][f], 68, wmma::mem_row_major);
            __syncthreads();
            #pragma unroll
            for (int i = 0; i < 16; i++) {
                int idx = tid + i * NTH, r = idx >> 6, c = idx & 63;
                float e = tanh_fast(stg[r * 68 + c] + __ldg(enc_b_ + b * 64 + c));
                Ebh[r * 72 + c] = __float2bfloat16(e);
            }
            if (b == 0) cpwait<0>();
            __syncthreads();
            #pragma unroll
            for (int ks = 0; ks < 4; ks++) {
                FragA ah[2];
                #pragma unroll
                for (int t = 0; t < 2; t++)
                    wmma::load_matrix_sync(ah[t], Ebh + (rm + 16 * t) * 72 + ks * 16, 72);
                FragBc bh, bl;
                wmma::load_matrix_sync(bh, Mh + (wn * 16) * 264 + b * 64 + ks * 16, 264);
                wmma::load_matrix_sync(bl, Ml + (wn * 16) * 264 + b * 64 + ks * 16, 264);
                #pragma unroll
                for (int t = 0; t < 2; t++) {
                    wmma::mma_sync(acc2[t], ah[t], bh, acc2[t]);
                    wmma::mma_sync(acc2[t], ah[t], bl, acc2[t]);
                }
            }
            __syncthreads();
        }
        #pragma unroll
        for (int t = 0; t < 2; t++)
            wmma::store_matrix_sync(stg + (rm + 16 * t) * 68 + wn * 16, acc2[t], 68,
                                    wmma::mem_row_major);
        __syncthreads();
    }

    // ====== softmax (threads 0..63) + attn tiles (h/l, unchanged) ======
    {
        __nv_bfloat16* Ah = (__nv_bfloat16*)(smem + ATH_O);
        __nv_bfloat16* Al = (__nv_bfloat16*)(smem + ATL_O);
        if (tid < 64) {
            float* lr = (float*)(smem + STG_O) + tid * 68;
            float m = -1e30f;
            #pragma unroll
            for (int c = 0; c < 64; c++) m = fmaxf(m, lr[c]);
            float sum = 0.f;
            #pragma unroll
            for (int c = 0; c < 64; c++) {
                float e = __expf((lr[c] - m) * 0.0625f);
                lr[c] = e; sum += e;
            }
            float inv = 1.0f / sum;
            float* arow = att + (row0 + tid) * 64;
            #pragma unroll
            for (int c = 0; c < 64; c += 4) {
                float4 v = *(float4*)(lr + c);
                v.x *= inv; v.y *= inv; v.z *= inv; v.w *= inv;
                *(float4*)(arow + c) = v;
                uint16_t h, l;
                split1(v.x, h, l); Ah[tid*72+c]   = __ushort_as_bfloat16(h); Al[tid*72+c]   = __ushort_as_bfloat16(l);
                split1(v.y, h, l); Ah[tid*72+c+1] = __ushort_as_bfloat16(h); Al[tid*72+c+1] = __ushort_as_bfloat16(l);
                split1(v.z, h, l); Ah[tid*72+c+2] = __ushort_as_bfloat16(h); Al[tid*72+c+2] = __ushort_as_bfloat16(l);
                split1(v.w, h, l); Ah[tid*72+c+3] = __ushort_as_bfloat16(h); Al[tid*72+c+3] = __ushort_as_bfloat16(l);
            }
        }
        __syncthreads();
    }

    // ---- prefetch GEMM4 q=0 into buf0 ----
    #pragma unroll
    for (int i = 0; i < 2; i++) {
        int o = tid + i * NTH, r = o >> 2, sg = o & 3;
        cpa(sb + B4H(0) + r * 80 + sg * 16, g_dwh + r * 256 + sg * 8);
        cpa(sb + B4L(0) + r * 80 + sg * 16, g_dwl + r * 256 + sg * 8);
    }
    cpcommit();

    // ================== GEMM3: M = attn @ mem (3-term, unchanged) ==================
    FragC acc3[2][4];
    #pragma unroll
    for (int t = 0; t < 2; t++)
        #pragma unroll
        for (int f = 0; f < 4; f++) wmma::fill_fragment(acc3[t][f], 0.0f);
    {
        const __nv_bfloat16* Ah = (const __nv_bfloat16*)(smem + ATH_O);
        const __nv_bfloat16* Al = (const __nv_bfloat16*)(smem + ATL_O);
        const __nv_bfloat16* Mh = (const __nv_bfloat16*)(smem + MEMH_O);
        const __nv_bfloat16* Ml = (const __nv_bfloat16*)(smem + MEML_O);
        #pragma unroll
        for (int ks = 0; ks < 4; ks++) {
            FragA ah[2], al[2];
            #pragma unroll
            for (int t = 0; t < 2; t++) {
                wmma::load_matrix_sync(ah[t], Ah + (rm + 16 * t) * 72 + ks * 16, 72);
                wmma::load_matrix_sync(al[t], Al + (rm + 16 * t) * 72 + ks * 16, 72);
            }
            #pragma unroll
            for (int f = 0; f < 4; f++) {
                FragBr bh, bl;
                wmma::load_matrix_sync(bh, Mh + (ks * 16) * 264 + wn * 64 + f * 16, 264);
                wmma::load_matrix_sync(bl, Ml + (ks * 16) * 264 + wn * 64 + f * 16, 264);
                #pragma unroll
                for (int t = 0; t < 2; t++) {
                    wmma::mma_sync(acc3[t][f], ah[t], bh, acc3[t][f]);
                    wmma::mma_sync(acc3[t][f], ah[t], bl, acc3[t][f]);
                    wmma::mma_sync(acc3[t][f], al[t], bh, acc3[t][f]);
                }
            }
        }
    }
    __syncthreads();

    // ---- M epilogue: staggered staging (R11 verbatim) ----
    {
        float* stg = (float*)(smem + MSTG_O);
        __nv_bfloat16* Mh = (__nv_bfloat16*)(smem + MH_O);
        __nv_bfloat16* Ml = (__nv_bfloat16*)(smem + ML_O);
        for (int q = 0; q < 4; q++) {
            if (wn == q)
                #pragma unroll
                for (int t = 0; t < 2; t++)
                    #pragma unroll
                    for (int f = 0; f < 4; f++)
                        wmma::store_matrix_sync(stg + (rm + 16 * t) * 68 + f * 16,
                                                acc3[t][f], 68, wmma::mem_row_major);
            __syncthreads();
            #pragma unroll
            for (int i = 0; i < 16; i++) {
                int idx = tid + i * NTH, r = idx >> 6, c = idx & 63;
                int gn = q * 64 + c;
                float v = stg[r * 68 + c];
                memout[(row0 + r) * 256 + gn] = v;
                uint16_t h, l; split1(v, h, l);
                Mh[r * 264 + gn] = __ushort_as_bfloat16(h);
                Ml[r * 264 + gn] = __ushort_as_bfloat16(l);
            }
            __syncthreads();
        }
    }

    // ================== GEMM4: recon = M @ dec_w^T + dec_b (R11 verbatim) ==================
    {
        const __nv_bfloat16* Mh = (const __nv_bfloat16*)(smem + MH_O);
        const __nv_bfloat16* Ml = (const __nv_bfloat16*)(smem + ML_O);
        FragC acc4[2][2];
        for (int q = 0; q < 32; q++) {
            const int nt = q >> 3, kc = q & 7, buf = q & 1;
            if (kc == 0) {
                #pragma unroll
                for (int t = 0; t < 2; t++)
                    #pragma unroll
                    for (int f = 0; f < 2; f++) wmma::fill_fragment(acc4[t][f], 0.0f);
            }
            if (q < 31) {
                const int qp = q + 1, ntn = qp >> 3, kcn = qp & 7, nb = buf ^ 1;
                #pragma unroll
                for (int i = 0; i < 2; i++) {
                    int o = tid + i * NTH, r = o >> 2, sg = o & 3;
                    cpa(sb + B4H(nb) + r * 80 + sg * 16,
                        g_dwh + (ntn * 128 + r) * 256 + kcn * 32 + sg * 8);
                    cpa(sb + B4L(nb) + r * 80 + sg * 16,
                        g_dwl + (ntn * 128 + r) * 256 + kcn * 32 + sg * 8);
                }
                cpcommit(); cpwait<1>();
            } else cpwait<0>();
            __syncthreads();
            const __nv_bfloat16* Bh = (const __nv_bfloat16*)(smem + B4H(buf));
            const __nv_bfloat16* Bl = (const __nv_bfloat16*)(smem + B4L(buf));
            #pragma unroll
            for (int ks = 0; ks < 2; ks++) {
                FragA ah[2], al[2];
                #pragma unroll
                for (int t = 0; t < 2; t++) {
                    wmma::load_matrix_sync(ah[t], Mh + (rm + 16 * t) * 264 + kc * 32 + ks * 16, 264);
                    wmma::load_matrix_sync(al[t], Ml + (rm + 16 * t) * 264 + kc * 32 + ks * 16, 264);
                }
                #pragma unroll
                for (int f = 0; f < 2; f++) {
                    FragBc bh, bl;
                    wmma::load_matrix_sync(bh, Bh + (wn * 32 + f * 16) * 40 + ks * 16, 40);
                    wmma::load_matrix_sync(bl, Bl + (wn * 32 + f * 16) * 40 + ks * 16, 40);
                    #pragma unroll
                    for (int t = 0; t < 2; t++) {
                        wmma::mma_sync(acc4[t][f], ah[t], bh, acc4[t][f]);
                        wmma::mma_sync(acc4[t][f], ah[t], bl, acc4[t][f]);
                        wmma::mma_sync(acc4[t][f], al[t], bh, acc4[t][f]);
                    }
                }
            }
            __syncthreads();
            if (kc == 7) {
                float* stg = (float*)(smem + MSTG_O);
                for (int f = 0; f < 2; f++) {
                    #pragma unroll
                    for (int t = 0; t < 2; t++)
                        wmma::store_matrix_sync(stg + (rm + 16 * t) * 68 + wn * 16,
                                                acc4[t][f], 68, wmma::mem_row_major);
                    __syncthreads();
                    #pragma unroll
                    for (int i = 0; i < 16; i++) {
                        int idx = tid + i * NTH, r = idx >> 6, c = idx & 63;
                        int gn = (c >> 4) * 32 + f * 16 + (c & 15);
                        int d = nt * 128 + gn;
                        recon[(row0 + r) * 512 + d] = stg[r * 68 + c] + __ldg(dec_b_ + d);
                    }
                    __syncthreads();
                }
            }
        }
    }
}

extern "C" void kernel_launch(void* const* d_in, const int* in_sizes, int n_in,
                              void* d_out, int out_size)
{
    const float* seq   = (const float*)d_in[0];
    const float* enc_w = (const float*)d_in[1];
    const float* enc_b = (const float*)d_in[2];
    const float* memw  = (const float*)d_in[3];
    const float* dec_w = (const float*)d_in[4];
    const float* dec_b = (const float*)d_in[5];

    const long R = (long)in_sizes[0] / 512;   // 65536

    float* out    = (float*)d_out;
    float* recon  = out;
    float* att    = out + R * 512;
    float* memout = att + R * 64;

    split_small<<<272, 256>>>((const float4*)enc_w, (const float4*)dec_w, (const float4*)memw);

    cudaFuncSetAttribute(mwm9, cudaFuncAttributeMaxDynamicSharedMemorySize, SMEM_TOTAL);
    mwm9<<<(unsigned)(R / 64), NTH, SMEM_TOTAL>>>(seq, enc_b, dec_b, recon, att, memout);
}

// round 14
// speedup vs baseline: 1.2581x; 1.1601x over previous
#include <cuda_runtime.h>
#include <cuda_bf16.h>
#include <mma.h>
#include <stdint.h>
#include <math.h>
using namespace nvcuda;

#define NTH 256

__device__ __nv_bfloat16 g_ewh[256 * 512], g_ewl[256 * 512];
__device__ __nv_bfloat16 g_dwh[512 * 256], g_dwl[512 * 256];
__device__ __nv_bfloat16 g_mh[64 * 256],  g_ml[64 * 256];

#define XH(b)  ((b) * 10240)
#define WH(b)  (20480 + (b) * 40960)
#define STG_O  0
#define MEMH_O 20480
#define MEML_O 54272
#define EBH_O  88064
#define ATH_O  88064
#define ATL_O  97280
#define MSTG_O 88064
#define MH_O   20480
#define ML_O   54272
#define B4H(b) ((b) ? 88064 : 0)
#define B4L(b) ((b) ? 98304 : 10240)
#define SMEM_TOTAL 108544

typedef wmma::fragment<wmma::matrix_a, 16,16,16, __nv_bfloat16, wmma::row_major> FragA;
typedef wmma::fragment<wmma::matrix_b, 16,16,16, __nv_bfloat16, wmma::col_major> FragBc;
typedef wmma::fragment<wmma::matrix_b, 16,16,16, __nv_bfloat16, wmma::row_major> FragBr;
typedef wmma::fragment<wmma::accumulator, 16,16,16, float> FragC;

__device__ __forceinline__ float tanh_fast(float x) {
    float r;
    asm("tanh.approx.f32 %0, %1;" : "=f"(r) : "f"(x));
    return r;
}
__device__ __forceinline__ uint32_t bfpair(float a, float b) {
    __nv_bfloat162 t = __floats2bfloat162_rn(a, b);
    return *reinterpret_cast<uint32_t*>(&t);
}
__device__ __forceinline__ void split4(const float4 v, uint2 &h, uint2 &l) {
    __nv_bfloat16 hx = __float2bfloat16(v.x), hy = __float2bfloat16(v.y);
    __nv_bfloat16 hz = __float2bfloat16(v.z), hw = __float2bfloat16(v.w);
    h.x = ((uint32_t)__bfloat16_as_ushort(hy) << 16) | (uint32_t)__bfloat16_as_ushort(hx);
    h.y = ((uint32_t)__bfloat16_as_ushort(hw) << 16) | (uint32_t)__bfloat16_as_ushort(hz);
    l.x = bfpair(v.x - __bfloat162float(hx), v.y - __bfloat162float(hy));
    l.y = bfpair(v.z - __bfloat162float(hz), v.w - __bfloat162float(hw));
}
__device__ __forceinline__ uint2 pack4h(const float4 v) {
    uint2 h;
    h.x = bfpair(v.x, v.y);
    h.y = bfpair(v.z, v.w);
    return h;
}
__device__ __forceinline__ void split1(float v, uint16_t &h, uint16_t &l) {
    __nv_bfloat16 hv = __float2bfloat16(v);
    h = __bfloat16_as_ushort(hv);
    l = __bfloat16_as_ushort(__float2bfloat16(v - __bfloat162float(hv)));
}
__device__ __forceinline__ void cpa(uint32_t s, const void* g) {
    asm volatile("cp.async.ca.shared.global [%0], [%1], 16;" :: "r"(s), "l"(g));
}
__device__ __forceinline__ void cpcommit() { asm volatile("cp.async.commit_group;"); }
template<int N> __device__ __forceinline__ void cpwait() {
    asm volatile("cp.async.wait_group %0;" :: "n"(N));
}

__global__ void split_small(const float4* __restrict__ ew, const float4* __restrict__ dw,
                            const float4* __restrict__ mw) {
    int i = blockIdx.x * blockDim.x + threadIdx.x;
    if (i < 32768) {
        uint2 h, l; split4(ew[i], h, l);
        ((uint2*)g_ewh)[i] = h; ((uint2*)g_ewl)[i] = l;
    } else if (i < 65536) {
        int j = i - 32768;
        uint2 h, l; split4(dw[j], h, l);
        ((uint2*)g_dwh)[j] = h; ((uint2*)g_dwl)[j] = l;
    } else if (i < 69632) {
        int j = i - 65536;
        uint2 h, l; split4(mw[j], h, l);
        ((uint2*)g_mh)[j] = h; ((uint2*)g_ml)[j] = l;
    }
}

__global__ __launch_bounds__(NTH, 2)
void mwm10(const float* __restrict__ seq,
           const float* __restrict__ enc_b_, const float* __restrict__ dec_b_,
           float* __restrict__ recon, float* __restrict__ att, float* __restrict__ memout)
{
    extern __shared__ char smem[];
    uint32_t sb;
    asm("{ .reg .u64 t; cvta.to.shared.u64 t, %1; cvt.u32.u64 %0, t; }" : "=r"(sb) : "l"(smem));
    const int tid = threadIdx.x, wid = tid >> 5;
    const int wm = wid & 1, wn = wid >> 1;
    const int rm = wm * 32;
    const long row0 = (long)blockIdx.x * 64;

    const int xr = tid >> 2, xq = (tid & 3) * 8;
    const float* xsrc = seq + (row0 + xr) * 512 + xq;

    auto xconv = [&](float4* rx, int b) {
        uint2 h0 = pack4h(rx[0]);
        uint2 h1 = pack4h(rx[1]);
        __nv_bfloat16* Xh = (__nv_bfloat16*)(smem + XH(b));
        *(uint2*)(Xh + xr * 40 + xq)     = h0;
        *(uint2*)(Xh + xr * 40 + xq + 4) = h1;
    };

    // ================== GEMM1 mainloop: 1-term (Xh·Wh only) ==================
    FragC acc1[2][4];
    #pragma unroll
    for (int t = 0; t < 2; t++)
        #pragma unroll
        for (int f = 0; f < 4; f++) wmma::fill_fragment(acc1[t][f], 0.0f);

    float4 rx[2][2];
    {
        rx[0][0] = *(const float4*)(xsrc);
        rx[0][1] = *(const float4*)(xsrc + 4);
        rx[1][0] = *(const float4*)(xsrc + 32);
        rx[1][1] = *(const float4*)(xsrc + 36);
        xconv(rx[0], 0);
        #pragma unroll
        for (int i = 0; i < 4; i++) {
            int o = tid + i * NTH, wr = o >> 2, ws = o & 3;
            cpa(sb + WH(0) + wr * 80 + ws * 16, g_ewh + wr * 512 + ws * 8);
        }
        cpcommit();
    }
    for (int kc = 0; kc < 16; kc++) {
        const int buf = kc & 1;
        if (kc < 15) {
            const int nb = buf ^ 1, kn = kc + 1;
            #pragma unroll
            for (int i = 0; i < 4; i++) {
                int o = tid + i * NTH, wr = o >> 2, ws = o & 3;
                cpa(sb + WH(nb) + wr * 80 + ws * 16, g_ewh + wr * 512 + kn * 32 + ws * 8);
            }
            cpcommit();
            xconv(rx[nb], nb);
            if (kc < 14) {
                rx[buf][0] = *(const float4*)(xsrc + (kc + 2) * 32);
                rx[buf][1] = *(const float4*)(xsrc + (kc + 2) * 32 + 4);
            }
            cpwait<1>();
        } else cpwait<0>();
        __syncthreads();
        const __nv_bfloat16* Xh = (const __nv_bfloat16*)(smem + XH(buf));
        const __nv_bfloat16* Wh = (const __nv_bfloat16*)(smem + WH(buf));
        #pragma unroll
        for (int ks = 0; ks < 2; ks++) {
            FragA ah[2];
            #pragma unroll
            for (int t = 0; t < 2; t++)
                wmma::load_matrix_sync(ah[t], Xh + (rm + 16 * t) * 40 + ks * 16, 40);
            #pragma unroll
            for (int f = 0; f < 4; f++) {
                FragBc bh;
                wmma::load_matrix_sync(bh, Wh + (wn * 64 + f * 16) * 40 + ks * 16, 40);
                #pragma unroll
                for (int t = 0; t < 2; t++)
                    wmma::mma_sync(acc1[t][f], ah[t], bh, acc1[t][f]);
            }
        }
        __syncthreads();
    }

    // ---- load memory bank tile [64][264] h/l ----
    #pragma unroll
    for (int i = 0; i < 8; i++) {
        int o = tid + i * NTH, s = o >> 5, c8 = o & 31;
        cpa(sb + MEMH_O + s * 528 + c8 * 16, g_mh + s * 256 + c8 * 8);
        cpa(sb + MEML_O + s * 528 + c8 * 16, g_ml + s * 256 + c8 * 8);
    }
    cpcommit();

    // ====== GEMM1 epilogue fused with GEMM2: E single bf16, GEMM2 2-pass ======
    FragC acc2[2];
    wmma::fill_fragment(acc2[0], 0.0f);
    wmma::fill_fragment(acc2[1], 0.0f);
    {
        float* stg = (float*)(smem + STG_O);
        __nv_bfloat16* Ebh = (__nv_bfloat16*)(smem + EBH_O);
        const __nv_bfloat16* Mh = (const __nv_bfloat16*)(smem + MEMH_O);
        const __nv_bfloat16* Ml = (const __nv_bfloat16*)(smem + MEML_O);
        for (int b = 0; b < 4; b++) {
            if (wn == b)
                #pragma unroll
                for (int t = 0; t < 2; t++)
                    #pragma unroll
                    for (int f = 0; f < 4; f++)
                        wmma::store_matrix_sync(stg + (rm + 16 * t) * 68 + f * 16,
                                                acc1[t][f], 68, wmma::mem_row_major);
            __syncthreads();
            #pragma unroll
            for (int i = 0; i < 16; i++) {
                int idx = tid + i * NTH, r = idx >> 6, c = idx & 63;
                float e = tanh_fast(stg[r * 68 + c] + __ldg(enc_b_ + b * 64 + c));
                Ebh[r * 72 + c] = __float2bfloat16(e);
            }
            if (b == 0) cpwait<0>();
            __syncthreads();
            #pragma unroll
            for (int ks = 0; ks < 4; ks++) {
                FragA ah[2];
                #pragma unroll
                for (int t = 0; t < 2; t++)
                    wmma::load_matrix_sync(ah[t], Ebh + (rm + 16 * t) * 72 + ks * 16, 72);
                FragBc bh, bl;
                wmma::load_matrix_sync(bh, Mh + (wn * 16) * 264 + b * 64 + ks * 16, 264);
                wmma::load_matrix_sync(bl, Ml + (wn * 16) * 264 + b * 64 + ks * 16, 264);
                #pragma unroll
                for (int t = 0; t < 2; t++) {
                    wmma::mma_sync(acc2[t], ah[t], bh, acc2[t]);
                    wmma::mma_sync(acc2[t], ah[t], bl, acc2[t]);
                }
            }
            __syncthreads();
        }
        #pragma unroll
        for (int t = 0; t < 2; t++)
            wmma::store_matrix_sync(stg + (rm + 16 * t) * 68 + wn * 16, acc2[t], 68,
                                    wmma::mem_row_major);
        __syncthreads();
    }

    // ====== softmax (threads 0..63) + attn tiles ======
    {
        __nv_bfloat16* Ah = (__nv_bfloat16*)(smem + ATH_O);
        __nv_bfloat16* Al = (__nv_bfloat16*)(smem + ATL_O);
        if (tid < 64) {
            float* lr = (float*)(smem + STG_O) + tid * 68;
            float m = -1e30f;
            #pragma unroll
            for (int c = 0; c < 64; c++) m = fmaxf(m, lr[c]);
            float sum = 0.f;
            #pragma unroll
            for (int c = 0; c < 64; c++) {
                float e = __expf((lr[c] - m) * 0.0625f);
                lr[c] = e; sum += e;
            }
            float inv = 1.0f / sum;
            float* arow = att + (row0 + tid) * 64;
            #pragma unroll
            for (int c = 0; c < 64; c += 4) {
                float4 v = *(float4*)(lr + c);
                v.x *= inv; v.y *= inv; v.z *= inv; v.w *= inv;
                *(float4*)(arow + c) = v;
                uint16_t h, l;
                split1(v.x, h, l); Ah[tid*72+c]   = __ushort_as_bfloat16(h); Al[tid*72+c]   = __ushort_as_bfloat16(l);
                split1(v.y, h, l); Ah[tid*72+c+1] = __ushort_as_bfloat16(h); Al[tid*72+c+1] = __ushort_as_bfloat16(l);
                split1(v.z, h, l); Ah[tid*72+c+2] = __ushort_as_bfloat16(h); Al[tid*72+c+2] = __ushort_as_bfloat16(l);
                split1(v.w, h, l); Ah[tid*72+c+3] = __ushort_as_bfloat16(h); Al[tid*72+c+3] = __ushort_as_bfloat16(l);
            }
        }
        __syncthreads();
    }

    // ---- prefetch GEMM4 q=0 into buf0 ----
    #pragma unroll
    for (int i = 0; i < 2; i++) {
        int o = tid + i * NTH, r = o >> 2, sg = o & 3;
        cpa(sb + B4H(0) + r * 80 + sg * 16, g_dwh + r * 256 + sg * 8);
        cpa(sb + B4L(0) + r * 80 + sg * 16, g_dwl + r * 256 + sg * 8);
    }
    cpcommit();

    // ================== GEMM3: M = attn @ mem (3-term) ==================
    FragC acc3[2][4];
    #pragma unroll
    for (int t = 0; t < 2; t++)
        #pragma unroll
        for (int f = 0; f < 4; f++) wmma::fill_fragment(acc3[t][f], 0.0f);
    {
        const __nv_bfloat16* Ah = (const __nv_bfloat16*)(smem + ATH_O);
        const __nv_bfloat16* Al = (const __nv_bfloat16*)(smem + ATL_O);
        const __nv_bfloat16* Mh = (const __nv_bfloat16*)(smem + MEMH_O);
        const __nv_bfloat16* Ml = (const __nv_bfloat16*)(smem + MEML_O);
        #pragma unroll
        for (int ks = 0; ks < 4; ks++) {
            FragA ah[2], al[2];
            #pragma unroll
            for (int t = 0; t < 2; t++) {
                wmma::load_matrix_sync(ah[t], Ah + (rm + 16 * t) * 72 + ks * 16, 72);
                wmma::load_matrix_sync(al[t], Al + (rm + 16 * t) * 72 + ks * 16, 72);
            }
            #pragma unroll
            for (int f = 0; f < 4; f++) {
                FragBr bh, bl;
                wmma::load_matrix_sync(bh, Mh + (ks * 16) * 264 + wn * 64 + f * 16, 264);
                wmma::load_matrix_sync(bl, Ml + (ks * 16) * 264 + wn * 64 + f * 16, 264);
                #pragma unroll
                for (int t = 0; t < 2; t++) {
                    wmma::mma_sync(acc3[t][f], ah[t], bh, acc3[t][f]);
                    wmma::mma_sync(acc3[t][f], ah[t], bl, acc3[t][f]);
                    wmma::mma_sync(acc3[t][f], al[t], bh, acc3[t][f]);
                }
            }
        }
    }
    __syncthreads();

    // ---- M epilogue: staggered staging ----
    {
        float* stg = (float*)(smem + MSTG_O);
        __nv_bfloat16* Mh = (__nv_bfloat16*)(smem + MH_O);
        __nv_bfloat16* Ml = (__nv_bfloat16*)(smem + ML_O);
        for (int q = 0; q < 4; q++) {
            if (wn == q)
                #pragma unroll
                for (int t = 0; t < 2; t++)
                    #pragma unroll
                    for (int f = 0; f < 4; f++)
                        wmma::store_matrix_sync(stg + (rm + 16 * t) * 68 + f * 16,
                                                acc3[t][f], 68, wmma::mem_row_major);
            __syncthreads();
            #pragma unroll
            for (int i = 0; i < 16; i++) {
                int idx = tid + i * NTH, r = idx >> 6, c = idx & 63;
                int gn = q * 64 + c;
                float v = stg[r * 68 + c];
                memout[(row0 + r) * 256 + gn] = v;
                uint16_t h, l; split1(v, h, l);
                Mh[r * 264 + gn] = __ushort_as_bfloat16(h);
                Ml[r * 264 + gn] = __ushort_as_bfloat16(l);
            }
            __syncthreads();
        }
    }

    // ================== GEMM4: recon = M @ dec_w^T + dec_b (3-term) ==================
    {
        const __nv_bfloat16* Mh = (const __nv_bfloat16*)(smem + MH_O);
        const __nv_bfloat16* Ml = (const __nv_bfloat16*)(smem + ML_O);
        FragC acc4[2][2];
        for (int q = 0; q < 32; q++) {
            const int nt = q >> 3, kc = q & 7, buf = q & 1;
            if (kc == 0) {
                #pragma unroll
                for (int t = 0; t < 2; t++)
                    #pragma unroll
                    for (int f = 0; f < 2; f++) wmma::fill_fragment(acc4[t][f], 0.0f);
            }
            if (q < 31) {
                const int qp = q + 1, ntn = qp >> 3, kcn = qp & 7, nb = buf ^ 1;
                #pragma unroll
                for (int i = 0; i < 2; i++) {
                    int o = tid + i * NTH, r = o >> 2, sg = o & 3;
                    cpa(sb + B4H(nb) + r * 80 + sg * 16,
                        g_dwh + (ntn * 128 + r) * 256 + kcn * 32 + sg * 8);
                    cpa(sb + B4L(nb) + r * 80 + sg * 16,
                        g_dwl + (ntn * 128 + r) * 256 + kcn * 32 + sg * 8);
                }
                cpcommit(); cpwait<1>();
            } else cpwait<0>();
            __syncthreads();
            const __nv_bfloat16* Bh = (const __nv_bfloat16*)(smem + B4H(buf));
            const __nv_bfloat16* Bl = (const __nv_bfloat16*)(smem + B4L(buf));
            #pragma unroll
            for (int ks = 0; ks < 2; ks++) {
                FragA ah[2], al[2];
                #pragma unroll
                for (int t = 0; t < 2; t++) {
                    wmma::load_matrix_sync(ah[t], Mh + (rm + 16 * t) * 264 + kc * 32 + ks * 16, 264);
                    wmma::load_matrix_sync(al[t], Ml + (rm + 16 * t) * 264 + kc * 32 + ks * 16, 264);
                }
                #pragma unroll
                for (int f = 0; f < 2; f++) {
                    FragBc bh, bl;
                    wmma::load_matrix_sync(bh, Bh + (wn * 32 + f * 16) * 40 + ks * 16, 40);
                    wmma::load_matrix_sync(bl, Bl + (wn * 32 + f * 16) * 40 + ks * 16, 40);
                    #pragma unroll
                    for (int t = 0; t < 2; t++) {
                        wmma::mma_sync(acc4[t][f], ah[t], bh, acc4[t][f]);
                        wmma::mma_sync(acc4[t][f], ah[t], bl, acc4[t][f]);
                        wmma::mma_sync(acc4[t][f], al[t], bh, acc4[t][f]);
                    }
                }
            }
            __syncthreads();
            if (kc == 7) {
                float* stg = (float*)(smem + MSTG_O);
                for (int f = 0; f < 2; f++) {
                    #pragma unroll
                    for (int t = 0; t < 2; t++)
                        wmma::store_matrix_sync(stg + (rm + 16 * t) * 68 + wn * 16,
                                                acc4[t][f], 68, wmma::mem_row_major);
                    __syncthreads();
                    #pragma unroll
                    for (int i = 0; i < 16; i++) {
                        int idx = tid + i * NTH, r = idx >> 6, c = idx & 63;
                        int gn = (c >> 4) * 32 + f * 16 + (c & 15);
                        int d = nt * 128 + gn;
                        recon[(row0 + r) * 512 + d] = stg[r * 68 + c] + __ldg(dec_b_ + d);
                    }
                    __syncthreads();
                }
            }
        }
    }
}

extern "C" void kernel_launch(void* const* d_in, const int* in_sizes, int n_in,
                              void* d_out, int out_size)
{
    const float* seq   = (const float*)d_in[0];
    const float* enc_w = (const float*)d_in[1];
    const float* enc_b = (const float*)d_in[2];
    const float* memw  = (const float*)d_in[3];
    const float* dec_w = (const float*)d_in[4];
    const float* dec_b = (const float*)d_in[5];

    const long R = (long)in_sizes[0] / 512;   // 65536

    float* out    = (float*)d_out;
    float* recon  = out;
    float* att    = out + R * 512;
    float* memout = att + R * 64;

    split_small<<<272, 256>>>((const float4*)enc_w, (const float4*)dec_w, (const float4*)memw);

    cudaFuncSetAttribute(mwm10, cudaFuncAttributeMaxDynamicSharedMemorySize, SMEM_TOTAL);
    mwm10<<<(unsigned)(R / 64), NTH, SMEM_TOTAL>>>(seq, enc_b, dec_b, recon, att, memout);
}